// round 16
// baseline (speedup 1.0000x reference)
#include <cuda_runtime.h>
#include <cstdint>

#define BATCH 8
#define NNODES 50000
#define DIM 64
#define ROW_F4 16
#define MAX_E 1600000
#define WP 72   // smem weight row stride (floats): (4*kk+q)*WP -> banks 8q apart

__device__ int g_is64;
__device__ int g_row_start[NNODES + 1];
__device__ int g_cursor[NNODES];
__device__ int g_col[MAX_E];

// ---------------------------------------------------------------------------
// packed f32x2 helpers
// ---------------------------------------------------------------------------
__device__ __forceinline__ unsigned long long pack2(float a, float b) {
    unsigned long long r;
    asm("mov.b64 %0, {%1, %2};" : "=l"(r) : "f"(a), "f"(b));
    return r;
}
__device__ __forceinline__ unsigned long long fma2(unsigned long long a,
                                                   unsigned long long b,
                                                   unsigned long long c) {
    unsigned long long d;
    asm("fma.rn.f32x2 %0, %1, %2, %3;" : "=l"(d) : "l"(a), "l"(b), "l"(c));
    return d;
}
__device__ __forceinline__ unsigned long long add2(unsigned long long a,
                                                   unsigned long long b) {
    unsigned long long d;
    asm("add.rn.f32x2 %0, %1, %2;" : "=l"(d) : "l"(a), "l"(b));
    return d;
}
__device__ __forceinline__ void unpack2(unsigned long long v, float& lo, float& hi) {
    asm("mov.b64 {%0, %1}, %2;" : "=f"(lo), "=f"(hi) : "l"(v));
}
__device__ __forceinline__ void add4(float4& a, const float4& v) {
    a.x += v.x; a.y += v.y; a.z += v.z; a.w += v.w;
}

__device__ __forceinline__ int edge_count(int is64, int nwords) {
    if (is64) return (nwords >= 3000000) ? (nwords >> 2) : (nwords >> 1);
    return nwords >> 1;
}
__device__ __forceinline__ void load_edge(const void* raw, int is64, int e,
                                          int& s, int& d) {
    if (is64) {
        const long long* p = (const long long*)raw;
        s = (int)p[2 * (long long)e];
        d = (int)p[2 * (long long)e + 1];
    } else {
        const int* p = (const int*)raw;
        s = p[2 * e];
        d = p[2 * e + 1];
    }
}

// ---------------------------------------------------------------------------
// Kernel 0: detect edge dtype + zero per-node counters
// ---------------------------------------------------------------------------
__global__ void detect_dtype_kernel(const int* __restrict__ w, int nwords) {
    __shared__ int any_nonzero;
    if (threadIdx.x == 0) any_nonzero = 0;
    __syncthreads();
    int limit = nwords / 2;
    if (limit > 16384) limit = 16384;
    for (int i = threadIdx.x; i < limit; i += blockDim.x) {
        if (w[2 * i + 1] != 0) any_nonzero = 1;
    }
    __syncthreads();
    if (threadIdx.x == 0) g_is64 = (any_nonzero == 0) ? 1 : 0;
    for (int i = threadIdx.x; i < NNODES; i += blockDim.x) g_cursor[i] = 0;
}

// ---------------------------------------------------------------------------
// Kernel 1: per-dst degree histogram
// ---------------------------------------------------------------------------
__global__ void count_kernel(const void* __restrict__ edges, int nwords) {
    int is64 = g_is64;
    int n = edge_count(is64, nwords);
    int e = blockIdx.x * blockDim.x + threadIdx.x;
    if (e >= n) return;
    int s, d;
    load_edge(edges, is64, e, s, d);
    atomicAdd(&g_cursor[d], 1);
}

// ---------------------------------------------------------------------------
// Kernel 2: exclusive scan -> row_start; reset cursors
// ---------------------------------------------------------------------------
__global__ void scan_kernel() {
    __shared__ int part[1024];
    int t = threadIdx.x;
    const int chunk = (NNODES + 1023) / 1024;   // 49
    int begin = t * chunk;
    int end = begin + chunk;
    if (end > NNODES) end = NNODES;
    int s = 0;
    for (int i = begin; i < end; i++) s += g_cursor[i];
    part[t] = s;
    __syncthreads();
    for (int off = 1; off < 1024; off <<= 1) {
        int v = (t >= off) ? part[t - off] : 0;
        __syncthreads();
        part[t] += v;
        __syncthreads();
    }
    int offset = (t > 0) ? part[t - 1] : 0;
    for (int i = begin; i < end; i++) {
        int c = g_cursor[i];
        g_row_start[i] = offset;
        offset += c;
        g_cursor[i] = 0;
    }
    if (t == 1023) g_row_start[NNODES] = part[1023];
}

// ---------------------------------------------------------------------------
// Kernel 3: fill CSR column (src) lists
// ---------------------------------------------------------------------------
__global__ void fill_kernel(const void* __restrict__ edges, int nwords) {
    int is64 = g_is64;
    int n = edge_count(is64, nwords);
    int e = blockIdx.x * blockDim.x + threadIdx.x;
    if (e >= n) return;
    int s, d;
    load_edge(edges, is64, e, s, d);
    int pos = g_row_start[d] + atomicAdd(&g_cursor[d], 1);
    g_col[pos] = s;
}

// ---------------------------------------------------------------------------
// Kernel 4: FUSED gather + dual-GEMM + bias + ReLU. One warp per node
// (loops 2 nodes), all 8 batches per warp. Lane l = (batch b=l>>2, k-chunk
// q=l&3: k in [16q,16q+16)).
//   gather: accumulate agg[b][node][16q..16q+16) in regs (2-deep unroll).
//   gemm:   each lane computes partials for ALL 64 outputs over its 16 k's
//           (f32x2); weights from smem with interleaved rows r=4*kk+q,
//           stride WP=72 -> q-lanes hit disjoint bank groups (conflict-free).
//   reduce: 2-stage shfl_xor reduce-scatter over q -> lane q owns outputs
//           [16q,16q+16); + bias, relu, STG.128 x4.
// No g_agg scratch at all.
// ---------------------------------------------------------------------------
__global__ __launch_bounds__(128) void fused_gnn_kernel(
        const float* __restrict__ x,
        const float* __restrict__ Ws, const float* __restrict__ bs,
        const float* __restrict__ Wn, const float* __restrict__ bn,
        float* __restrict__ out) {
    __shared__ __align__(16) float sWs[64 * WP];
    __shared__ __align__(16) float sWn[64 * WP];
    __shared__ float sb[64];

    int tid = threadIdx.x;
    // stage weights, interleaved rows: k = 16q + kk -> row r = 4*kk + q
    for (int idx = tid; idx < DIM * DIM; idx += 128) {
        int o = idx >> 6;
        int k = idx & 63;
        int r = ((k & 15) << 2) | (k >> 4);
        sWs[r * WP + o] = Ws[idx];
        sWn[r * WP + o] = Wn[idx];
    }
    if (tid < DIM) sb[tid] = bs[tid] + bn[tid];
    __syncthreads();

    int warp = tid >> 5;
    int lane = tid & 31;
    int b = lane >> 2;
    int q = lane & 3;

    const float4* xb = reinterpret_cast<const float4*>(x) +
                       (size_t)b * NNODES * ROW_F4 + 4 * q;

#pragma unroll 1
    for (int nn = 0; nn < 2; nn++) {
        int node = blockIdx.x * 8 + warp * 2 + nn;
        if (node >= NNODES) break;

        int start = g_row_start[node];
        int end = g_row_start[node + 1];

        // ---- gather phase: agg chunk in A0..A3 ----
        float4 aA0 = {0,0,0,0}, aA1 = {0,0,0,0}, aA2 = {0,0,0,0}, aA3 = {0,0,0,0};
        float4 aB0 = {0,0,0,0}, aB1 = {0,0,0,0}, aB2 = {0,0,0,0}, aB3 = {0,0,0,0};

        for (int e0 = start; e0 < end; e0 += 32) {
            int cnt = end - e0;
            if (cnt > 32) cnt = 32;
            int my = (lane < cnt) ? g_col[e0 + lane] : 0;
            int t = 0;
            for (; t + 2 <= cnt; t += 2) {
                int s0 = __shfl_sync(0xffffffffu, my, t);
                int s1 = __shfl_sync(0xffffffffu, my, t + 1);
                const float4* p0 = xb + (size_t)s0 * ROW_F4;
                const float4* p1 = xb + (size_t)s1 * ROW_F4;
                float4 v00 = p0[0], v01 = p0[1], v02 = p0[2], v03 = p0[3];
                float4 v10 = p1[0], v11 = p1[1], v12 = p1[2], v13 = p1[3];
                add4(aA0, v00); add4(aA1, v01); add4(aA2, v02); add4(aA3, v03);
                add4(aB0, v10); add4(aB1, v11); add4(aB2, v12); add4(aB3, v13);
            }
            if (t < cnt) {
                int s0 = __shfl_sync(0xffffffffu, my, t);
                const float4* p0 = xb + (size_t)s0 * ROW_F4;
                float4 v00 = p0[0], v01 = p0[1], v02 = p0[2], v03 = p0[3];
                add4(aA0, v00); add4(aA1, v01); add4(aA2, v02); add4(aA3, v03);
            }
        }
        add4(aA0, aB0); add4(aA1, aB1); add4(aA2, aB2); add4(aA3, aB3);

        // lane's x chunk
        const float4* xr = xb + (size_t)node * ROW_F4;
        float4 X0 = xr[0], X1 = xr[1], X2 = xr[2], X3 = xr[3];

        // ---- gemm phase: partials for all 64 outputs over my 16 k's ----
        float xe[16] = {X0.x, X0.y, X0.z, X0.w, X1.x, X1.y, X1.z, X1.w,
                        X2.x, X2.y, X2.z, X2.w, X3.x, X3.y, X3.z, X3.w};
        float ae[16] = {aA0.x, aA0.y, aA0.z, aA0.w, aA1.x, aA1.y, aA1.z, aA1.w,
                        aA2.x, aA2.y, aA2.z, aA2.w, aA3.x, aA3.y, aA3.z, aA3.w};

        unsigned long long acc[32];
        unsigned long long z = pack2(0.f, 0.f);
#pragma unroll
        for (int j = 0; j < 32; j++) acc[j] = z;

#pragma unroll
        for (int kk = 0; kk < 16; kk++) {
            const ulonglong2* wsp =
                reinterpret_cast<const ulonglong2*>(&sWs[(kk * 4 + q) * WP]);
            const ulonglong2* wnp =
                reinterpret_cast<const ulonglong2*>(&sWn[(kk * 4 + q) * WP]);
            unsigned long long xp = pack2(xe[kk], xe[kk]);
            unsigned long long ap = pack2(ae[kk], ae[kk]);
#pragma unroll
            for (int oi = 0; oi < 16; oi++) {
                ulonglong2 w = wsp[oi];
                ulonglong2 u = wnp[oi];
                acc[2 * oi + 0] = fma2(xp, w.x, acc[2 * oi + 0]);
                acc[2 * oi + 0] = fma2(ap, u.x, acc[2 * oi + 0]);
                acc[2 * oi + 1] = fma2(xp, w.y, acc[2 * oi + 1]);
                acc[2 * oi + 1] = fma2(ap, u.y, acc[2 * oi + 1]);
            }
        }

        // ---- reduce-scatter over q (lanes b*4 + {0,1,2,3}) ----
        int bit1 = (q >> 1) & 1;
        int bit0 = q & 1;

        // stage 1 (xor 2): keep half [32*bit1, +32) = acc[16*bit1 .. +16)
        unsigned long long halfacc[16];
#pragma unroll
        for (int j = 0; j < 16; j++) {
            unsigned long long send = bit1 ? acc[j] : acc[16 + j];
            unsigned long long recv = __shfl_xor_sync(0xffffffffu, send, 2);
            unsigned long long keep = bit1 ? acc[16 + j] : acc[j];
            halfacc[j] = add2(keep, recv);
        }
        // stage 2 (xor 1): keep quarter -> outputs [16q, 16q+16)
        unsigned long long quart[8];
#pragma unroll
        for (int j = 0; j < 8; j++) {
            unsigned long long send = bit0 ? halfacc[j] : halfacc[8 + j];
            unsigned long long recv = __shfl_xor_sync(0xffffffffu, send, 1);
            unsigned long long keep = bit0 ? halfacc[8 + j] : halfacc[j];
            quart[j] = add2(keep, recv);
        }

        // ---- bias + relu + store ----
        const float* bq = sb + 16 * q;
        float4* orow = reinterpret_cast<float4*>(
            out + ((size_t)b * NNODES + (size_t)node) * DIM + 16 * q);
#pragma unroll
        for (int j2 = 0; j2 < 4; j2++) {
            float l0, h0, l1, h1;
            unpack2(quart[2 * j2 + 0], l0, h0);
            unpack2(quart[2 * j2 + 1], l1, h1);
            float4 r;
            r.x = fmaxf(l0 + bq[4 * j2 + 0], 0.f);
            r.y = fmaxf(h0 + bq[4 * j2 + 1], 0.f);
            r.z = fmaxf(l1 + bq[4 * j2 + 2], 0.f);
            r.w = fmaxf(h1 + bq[4 * j2 + 3], 0.f);
            orow[j2] = r;
        }
    }
}

// ---------------------------------------------------------------------------
// Launch
// ---------------------------------------------------------------------------
extern "C" void kernel_launch(void* const* d_in, const int* in_sizes, int n_in,
                              void* d_out, int out_size) {
    const float* x = (const float*)d_in[0];
    const void* edges = d_in[1];
    const float* Ws = (const float*)d_in[2];
    const float* bs = (const float*)d_in[3];
    const float* Wn = (const float*)d_in[4];
    const float* bn = (const float*)d_in[5];
    float* out = (float*)d_out;

    int nwords = in_sizes[1];
    int max_edges = nwords / 2;
    int eblocks = (max_edges + 255) / 256;

    // CSR build
    detect_dtype_kernel<<<1, 256>>>((const int*)edges, nwords);
    count_kernel<<<eblocks, 256>>>(edges, nwords);
    scan_kernel<<<1, 1024>>>();
    fill_kernel<<<eblocks, 256>>>(edges, nwords);

    // fused gather + dual-GEMM + bias + relu: 4 warps x 2 nodes per block
    int fblocks = (NNODES + 7) / 8;   // 6250
    fused_gnn_kernel<<<fblocks, 128>>>(x, Ws, bs, Wn, bn, out);
}

// round 17
// speedup vs baseline: 1.8008x; 1.8008x over previous
#include <cuda_runtime.h>
#include <cstdint>

#define BATCH 8
#define NNODES 50000
#define DIM 64
#define ROW_F4 16
#define TOTAL_ROWS ((size_t)BATCH * NNODES)   // 400000
#define MAX_E 1600000

__device__ float4 g_agg[TOTAL_ROWS * ROW_F4];   // 102.4 MB, 16B-aligned
__device__ int g_is64;
__device__ int g_row_start[NNODES + 1];
__device__ int g_cursor[NNODES];
__device__ int g_col[MAX_E];

// ---------------------------------------------------------------------------
// packed f32x2 helpers
// ---------------------------------------------------------------------------
__device__ __forceinline__ unsigned long long pack2(float a, float b) {
    unsigned long long r;
    asm("mov.b64 %0, {%1, %2};" : "=l"(r) : "f"(a), "f"(b));
    return r;
}
__device__ __forceinline__ unsigned long long fma2(unsigned long long a,
                                                   unsigned long long b,
                                                   unsigned long long c) {
    unsigned long long d;
    asm("fma.rn.f32x2 %0, %1, %2, %3;" : "=l"(d) : "l"(a), "l"(b), "l"(c));
    return d;
}
__device__ __forceinline__ void unpack2(unsigned long long v, float& lo, float& hi) {
    asm("mov.b64 {%0, %1}, %2;" : "=f"(lo), "=f"(hi) : "l"(v));
}
__device__ __forceinline__ void add4(float4& a, const float4& v) {
    a.x += v.x; a.y += v.y; a.z += v.z; a.w += v.w;
}

__device__ __forceinline__ int edge_count(int is64, int nwords) {
    if (is64) return (nwords >= 3000000) ? (nwords >> 2) : (nwords >> 1);
    return nwords >> 1;
}
__device__ __forceinline__ void load_edge(const void* raw, int is64, int e,
                                          int& s, int& d) {
    if (is64) {
        const long long* p = (const long long*)raw;
        s = (int)p[2 * (long long)e];
        d = (int)p[2 * (long long)e + 1];
    } else {
        const int* p = (const int*)raw;
        s = p[2 * e];
        d = p[2 * e + 1];
    }
}

// ---------------------------------------------------------------------------
// Kernel 0: detect edge dtype + zero per-node counters
// ---------------------------------------------------------------------------
__global__ void detect_dtype_kernel(const int* __restrict__ w, int nwords) {
    __shared__ int any_nonzero;
    if (threadIdx.x == 0) any_nonzero = 0;
    __syncthreads();
    int limit = nwords / 2;
    if (limit > 16384) limit = 16384;
    for (int i = threadIdx.x; i < limit; i += blockDim.x) {
        if (w[2 * i + 1] != 0) any_nonzero = 1;
    }
    __syncthreads();
    if (threadIdx.x == 0) g_is64 = (any_nonzero == 0) ? 1 : 0;
    for (int i = threadIdx.x; i < NNODES; i += blockDim.x) g_cursor[i] = 0;
}

// ---------------------------------------------------------------------------
// Kernel 1: per-dst degree histogram
// ---------------------------------------------------------------------------
__global__ void count_kernel(const void* __restrict__ edges, int nwords) {
    int is64 = g_is64;
    int n = edge_count(is64, nwords);
    int e = blockIdx.x * blockDim.x + threadIdx.x;
    if (e >= n) return;
    int s, d;
    load_edge(edges, is64, e, s, d);
    atomicAdd(&g_cursor[d], 1);
}

// ---------------------------------------------------------------------------
// Kernel 2: exclusive scan -> row_start; reset cursors
// ---------------------------------------------------------------------------
__global__ void scan_kernel() {
    __shared__ int part[1024];
    int t = threadIdx.x;
    const int chunk = (NNODES + 1023) / 1024;   // 49
    int begin = t * chunk;
    int end = begin + chunk;
    if (end > NNODES) end = NNODES;
    int s = 0;
    for (int i = begin; i < end; i++) s += g_cursor[i];
    part[t] = s;
    __syncthreads();
    for (int off = 1; off < 1024; off <<= 1) {
        int v = (t >= off) ? part[t - off] : 0;
        __syncthreads();
        part[t] += v;
        __syncthreads();
    }
    int offset = (t > 0) ? part[t - 1] : 0;
    for (int i = begin; i < end; i++) {
        int c = g_cursor[i];
        g_row_start[i] = offset;
        offset += c;
        g_cursor[i] = 0;
    }
    if (t == 1023) g_row_start[NNODES] = part[1023];
}

// ---------------------------------------------------------------------------
// Kernel 3: fill CSR column (src) lists
// ---------------------------------------------------------------------------
__global__ void fill_kernel(const void* __restrict__ edges, int nwords) {
    int is64 = g_is64;
    int n = edge_count(is64, nwords);
    int e = blockIdx.x * blockDim.x + threadIdx.x;
    if (e >= n) return;
    int s, d;
    load_edge(edges, is64, e, s, d);
    int pos = g_row_start[d] + atomicAdd(&g_cursor[d], 1);
    g_col[pos] = s;
}

// ---------------------------------------------------------------------------
// Kernel 4: CSR gather, WAVEFRONT-OPTIMAL lane mapping.
// One warp per node, all 8 batches. Per edge, 4 LDG.128; instruction j
// covers batches {2j, 2j+1} contiguously: lane = (hb = lane>>4 -> batch
// parity, c = lane&15 -> float4 in row). Each LDG touches 4 lines FULLY
// consumed -> 16 wavefronts/edge (the floor; R9 layout cost 64).
// Lane keeps 4 accumulators (batch 2j+hb, chunk c). Stores coalesced.
// Also zeroes degree-0 nodes (no separate zero pass).
// ---------------------------------------------------------------------------
__global__ __launch_bounds__(256) void gather_kernel(const float* __restrict__ x) {
    int node = (int)((blockIdx.x * (size_t)blockDim.x + threadIdx.x) >> 5);
    if (node >= NNODES) return;
    int lane = threadIdx.x & 31;
    int hb = lane >> 4;         // batch parity within group
    int c = lane & 15;          // float4 chunk within row

    int start = g_row_start[node];
    int end = g_row_start[node + 1];

    const float4* x4 = reinterpret_cast<const float4*>(x);
    const float4* bp0 = x4 + ((size_t)(0 + hb) * NNODES) * ROW_F4 + c;
    const float4* bp1 = x4 + ((size_t)(2 + hb) * NNODES) * ROW_F4 + c;
    const float4* bp2 = x4 + ((size_t)(4 + hb) * NNODES) * ROW_F4 + c;
    const float4* bp3 = x4 + ((size_t)(6 + hb) * NNODES) * ROW_F4 + c;

    float4 aA0 = {0,0,0,0}, aA1 = {0,0,0,0}, aA2 = {0,0,0,0}, aA3 = {0,0,0,0};
    float4 aB0 = {0,0,0,0}, aB1 = {0,0,0,0}, aB2 = {0,0,0,0}, aB3 = {0,0,0,0};

    for (int e0 = start; e0 < end; e0 += 32) {
        int cnt = end - e0;
        if (cnt > 32) cnt = 32;
        int my = (lane < cnt) ? g_col[e0 + lane] : 0;
        int t = 0;
        for (; t + 2 <= cnt; t += 2) {
            int s0 = __shfl_sync(0xffffffffu, my, t);
            int s1 = __shfl_sync(0xffffffffu, my, t + 1);
            size_t o0 = (size_t)s0 * ROW_F4;
            size_t o1 = (size_t)s1 * ROW_F4;
            // 8 independent fully-coalesced LDG.128 in flight
            float4 v00 = bp0[o0], v01 = bp1[o0], v02 = bp2[o0], v03 = bp3[o0];
            float4 v10 = bp0[o1], v11 = bp1[o1], v12 = bp2[o1], v13 = bp3[o1];
            add4(aA0, v00); add4(aA1, v01); add4(aA2, v02); add4(aA3, v03);
            add4(aB0, v10); add4(aB1, v11); add4(aB2, v12); add4(aB3, v13);
        }
        if (t < cnt) {
            int s0 = __shfl_sync(0xffffffffu, my, t);
            size_t o0 = (size_t)s0 * ROW_F4;
            float4 v00 = bp0[o0], v01 = bp1[o0], v02 = bp2[o0], v03 = bp3[o0];
            add4(aA0, v00); add4(aA1, v01); add4(aA2, v02); add4(aA3, v03);
        }
    }
    add4(aA0, aB0); add4(aA1, aB1); add4(aA2, aB2); add4(aA3, aB3);

    size_t nodeoff = (size_t)node * ROW_F4 + c;
    g_agg[((size_t)(0 + hb) * NNODES) * ROW_F4 + nodeoff] = aA0;
    g_agg[((size_t)(2 + hb) * NNODES) * ROW_F4 + nodeoff] = aA1;
    g_agg[((size_t)(4 + hb) * NNODES) * ROW_F4 + nodeoff] = aA2;
    g_agg[((size_t)(6 + hb) * NNODES) * ROW_F4 + nodeoff] = aA3;
}

// ---------------------------------------------------------------------------
// Kernel 5: dual-GEMM + bias + ReLU (proven 177us shape). Block=256, 128 rows.
// ---------------------------------------------------------------------------
#define WSTRIDE 68
#define SX_OFF 0
#define SA_OFF (128 * 64)
#define SWS_OFF (2 * 128 * 64)
#define SWN_OFF (SWS_OFF + 64 * WSTRIDE)
#define SB_OFF (SWN_OFF + 64 * WSTRIDE)
#define SMEM_FLOATS (SB_OFF + 64)

__global__ __launch_bounds__(256) void gemm_relu_kernel(
        const float* __restrict__ x,
        const float* __restrict__ Ws, const float* __restrict__ bs,
        const float* __restrict__ Wn, const float* __restrict__ bn,
        float* __restrict__ out) {
    extern __shared__ float sm[];
    float* sX = sm + SX_OFF;
    float* sA = sm + SA_OFF;
    float* sWs = sm + SWS_OFF;
    float* sWn = sm + SWN_OFF;
    float* sb = sm + SB_OFF;

    int tid = threadIdx.x;
    size_t rowbase = (size_t)blockIdx.x * 128;

    {
        const float4* xg = reinterpret_cast<const float4*>(x + rowbase * DIM);
        const float4* ag = &g_agg[rowbase * ROW_F4];
        float4* sx4 = reinterpret_cast<float4*>(sX);
        float4* sa4 = reinterpret_cast<float4*>(sA);
#pragma unroll
        for (int t = 0; t < 8; t++) {
            int idx = tid + t * 256;
            sx4[idx] = xg[idx];
            sa4[idx] = __ldcs(&ag[idx]);
        }
    }
    for (int idx = tid; idx < DIM * DIM; idx += 256) {
        int o = idx >> 6;
        int k = idx & 63;
        sWs[k * WSTRIDE + o] = Ws[idx];
        sWn[k * WSTRIDE + o] = Wn[idx];
    }
    if (tid < DIM) sb[tid] = bs[tid] + bn[tid];
    __syncthreads();

    int warp = tid >> 5;
    int lane = tid & 31;
    int h = lane >> 4;
    int i = lane & 15;

    unsigned long long bias0 = pack2(sb[4 * i], sb[4 * i + 1]);
    unsigned long long bias1 = pack2(sb[4 * i + 2], sb[4 * i + 3]);
    unsigned long long acc[8][2];
#pragma unroll
    for (int j = 0; j < 8; j++) { acc[j][0] = bias0; acc[j][1] = bias1; }

    int row0 = warp * 16 + h;

#pragma unroll 1
    for (int c = 0; c < 16; c++) {
        int k0 = c * 4;
        unsigned long long wsv[4][2], wnv[4][2];
#pragma unroll
        for (int k = 0; k < 4; k++) {
            float4 w = *reinterpret_cast<const float4*>(&sWs[(k0 + k) * WSTRIDE + 4 * i]);
            wsv[k][0] = pack2(w.x, w.y);
            wsv[k][1] = pack2(w.z, w.w);
            float4 u = *reinterpret_cast<const float4*>(&sWn[(k0 + k) * WSTRIDE + 4 * i]);
            wnv[k][0] = pack2(u.x, u.y);
            wnv[k][1] = pack2(u.z, u.w);
        }
#pragma unroll
        for (int j = 0; j < 8; j++) {
            int r = row0 + 2 * j;
            float4 xv = *reinterpret_cast<const float4*>(&sX[r * DIM + k0]);
            float4 av = *reinterpret_cast<const float4*>(&sA[r * DIM + k0]);
            float xe[4] = {xv.x, xv.y, xv.z, xv.w};
            float ae[4] = {av.x, av.y, av.z, av.w};
#pragma unroll
            for (int k = 0; k < 4; k++) {
                unsigned long long xp = pack2(xe[k], xe[k]);
                unsigned long long ap = pack2(ae[k], ae[k]);
                acc[j][0] = fma2(xp, wsv[k][0], acc[j][0]);
                acc[j][0] = fma2(ap, wnv[k][0], acc[j][0]);
                acc[j][1] = fma2(xp, wsv[k][1], acc[j][1]);
                acc[j][1] = fma2(ap, wnv[k][1], acc[j][1]);
            }
        }
    }

#pragma unroll
    for (int j = 0; j < 8; j++) {
        size_t row = rowbase + (size_t)(row0 + 2 * j);
        float l0, h0, l1, h1;
        unpack2(acc[j][0], l0, h0);
        unpack2(acc[j][1], l1, h1);
        float4 r;
        r.x = fmaxf(l0, 0.f);
        r.y = fmaxf(h0, 0.f);
        r.z = fmaxf(l1, 0.f);
        r.w = fmaxf(h1, 0.f);
        __stcs(reinterpret_cast<float4*>(out + row * DIM + 4 * i), r);
    }
}

// ---------------------------------------------------------------------------
// Launch
// ---------------------------------------------------------------------------
extern "C" void kernel_launch(void* const* d_in, const int* in_sizes, int n_in,
                              void* d_out, int out_size) {
    const float* x = (const float*)d_in[0];
    const void* edges = d_in[1];
    const float* Ws = (const float*)d_in[2];
    const float* bs = (const float*)d_in[3];
    const float* Wn = (const float*)d_in[4];
    const float* bn = (const float*)d_in[5];
    float* out = (float*)d_out;

    int nwords = in_sizes[1];
    int max_edges = nwords / 2;
    int eblocks = (max_edges + 255) / 256;

    // CSR build
    detect_dtype_kernel<<<1, 256>>>((const int*)edges, nwords);
    count_kernel<<<eblocks, 256>>>(edges, nwords);
    scan_kernel<<<1, 1024>>>();
    fill_kernel<<<eblocks, 256>>>(edges, nwords);

    // gather: one warp per node (all batches), wavefront-optimal mapping
    gather_kernel<<<(NNODES + 7) / 8, 256>>>(x);

    // dual-GEMM + bias + relu
    int smem_bytes = SMEM_FLOATS * (int)sizeof(float);
    cudaFuncSetAttribute(gemm_relu_kernel,
                         cudaFuncAttributeMaxDynamicSharedMemorySize, smem_bytes);
    int gblocks = (int)(TOTAL_ROWS / 128);   // 3125
    gemm_relu_kernel<<<gblocks, 256, smem_bytes>>>(x, Ws, bs, Wn, bn, out);
}